// round 2
// baseline (speedup 1.0000x reference)
#include <cuda_runtime.h>

#define Bn 16
#define Hn 720
#define Wn 1280
#define PLANE (Hn * Wn)
#define NPIX (Bn * PLANE)
#define TPB 256
#define CHUNK (Wn / TPB)   // 5

// Accumulator: x = sum(-fx), y = sum(-fy), z = count, w = pad/has-flag.
// After the row pass it is repurposed:
//   valid pixel: {out_x, out_y, unused, 1}
//   hole pixel : {s_lr_x, s_lr_y, num_lr, 0}
__device__ float4 g_acc[NPIX];

// ---------------------------------------------------------------- zero
__global__ void k_zero() {
    int i = blockIdx.x * blockDim.x + threadIdx.x;
    if (i < NPIX) g_acc[i] = make_float4(0.f, 0.f, 0.f, 0.f);
}

// ---------------------------------------------------------------- scatter
__global__ void k_scatter(const float* __restrict__ in) {
    int p = blockIdx.x * blockDim.x + threadIdx.x;
    if (p >= PLANE) return;
    int b = blockIdx.y;
    int y = p / Wn;
    int x = p - y * Wn;

    float fx = in[(size_t)(2 * b    ) * PLANE + p];
    float fy = in[(size_t)(2 * b + 1) * PLANE + p];

    float x2 = (float)x + fx;
    float y2 = (float)y + fy;
    if (!(x2 >= 0.f && y2 >= 0.f && x2 <= (float)(Wn - 1) && y2 <= (float)(Hn - 1)))
        return;

    int xL = (int)floorf(x2); xL = max(0, min(xL, Wn - 1));
    int yT = (int)floorf(y2); yT = max(0, min(yT, Hn - 1));
    int xR = min(xL + 1, Wn - 1);
    int yB = min(yT + 1, Hn - 1);

    float4 v = make_float4(-fx, -fy, 1.f, 0.f);
    float4* a = g_acc + (size_t)b * PLANE;
    atomicAdd(&a[yT * Wn + xL], v);
    atomicAdd(&a[yT * Wn + xR], v);
    atomicAdd(&a[yB * Wn + xL], v);
    atomicAdd(&a[yB * Wn + xR], v);
}

// ------------------------------------------------- normalize + row fill
__global__ void k_row(float* __restrict__ outp) {
    __shared__ float sX[Wn];
    __shared__ float sY[Wn];
    __shared__ float sH[Wn];
    __shared__ int   sScan[TPB];

    int r = blockIdx.x;          // r = b*Hn + y
    int b = r / Hn;
    int y = r - b * Hn;
    size_t base = (size_t)r * Wn;
    int tid = threadIdx.x;

    // normalize into shared
    for (int i = tid; i < Wn; i += TPB) {
        float4 a = g_acc[base + i];
        bool  h   = (a.z > 0.f);
        float inv = h ? (1.f / a.z) : 0.f;
        sX[i] = a.x * inv;
        sY[i] = a.y * inv;
        sH[i] = h ? 1.f : 0.f;
    }
    __syncthreads();

    int x0 = tid * CHUNK;

    // left: nearest valid col <= x (inclusive cummax of valid col idx)
    int lloc[CHUNK];
    int lm = -1;
    #pragma unroll
    for (int k = 0; k < CHUNK; k++) {
        int xx = x0 + k;
        if (sH[xx] > 0.f) lm = xx;
        lloc[k] = lm;
    }
    sScan[tid] = lm;
    __syncthreads();
    for (int off = 1; off < TPB; off <<= 1) {
        int v = (tid >= off) ? sScan[tid - off] : -1;
        __syncthreads();
        if (v > sScan[tid]) sScan[tid] = v;
        __syncthreads();
    }
    int carryL = (tid > 0) ? sScan[tid - 1] : -1;
    __syncthreads();

    // right: nearest valid col >= x (reverse cummin)
    const int BIGI = 1 << 30;
    int rloc[CHUNK];
    int rm = BIGI;
    #pragma unroll
    for (int k = CHUNK - 1; k >= 0; k--) {
        int xx = x0 + k;
        if (sH[xx] > 0.f) rm = xx;
        rloc[k] = rm;
    }
    sScan[tid] = rm;
    __syncthreads();
    for (int off = 1; off < TPB; off <<= 1) {
        int v = (tid + off < TPB) ? sScan[tid + off] : BIGI;
        __syncthreads();
        if (v < sScan[tid]) sScan[tid] = v;
        __syncthreads();
    }
    int carryR = (tid < TPB - 1) ? sScan[tid + 1] : BIGI;

    float* outX = outp + ((size_t)(2 * b    ) * Hn + y) * Wn;
    float* outY = outp + ((size_t)(2 * b + 1) * Hn + y) * Wn;

    #pragma unroll
    for (int k = 0; k < CHUNK; k++) {
        int xx = x0 + k;
        float4 wout;
        if (sH[xx] > 0.f) {
            float ox = sX[xx], oy = sY[xx];
            outX[xx] = ox;
            outY[xx] = oy;
            wout = make_float4(ox, oy, 0.f, 1.f);
        } else {
            int L = max(carryL, lloc[k]);
            int R = min(carryR, rloc[k]);
            float sx = 0.f, sy = 0.f, num = 0.f;
            if (L >= 0) { sx += sX[L]; sy += sY[L]; num += 1.f; }
            if (R < Wn) { sx += sX[R]; sy += sY[R]; num += 1.f; }
            wout = make_float4(sx, sy, num, 0.f);
        }
        g_acc[base + xx] = wout;
    }
}

// ------------------------------------------------------- column fill
__global__ void k_col(float* __restrict__ outp) {
    int t = blockIdx.x * blockDim.x + threadIdx.x;
    if (t >= Bn * Wn) return;
    int b = t / Wn;
    int x = t - b * Wn;
    size_t base = (size_t)b * PLANE + x;

    // backward pass: add "down" (next valid below) contribution into partials
    float vdx = 0.f, vdy = 0.f, md = 0.f;
    for (int y = Hn - 1; y >= 0; y -= 4) {
        size_t i0 = base + (size_t)y * Wn;
        float4 a0 = g_acc[i0];
        float4 a1 = g_acc[i0 - Wn];
        float4 a2 = g_acc[i0 - 2 * Wn];
        float4 a3 = g_acc[i0 - 3 * Wn];

        if (a0.w > 0.5f) { vdx = a0.x; vdy = a0.y; md = 1.f; }
        else if (md > 0.f) { a0.x += vdx; a0.y += vdy; a0.z += 1.f; g_acc[i0] = a0; }
        if (a1.w > 0.5f) { vdx = a1.x; vdy = a1.y; md = 1.f; }
        else if (md > 0.f) { a1.x += vdx; a1.y += vdy; a1.z += 1.f; g_acc[i0 - Wn] = a1; }
        if (a2.w > 0.5f) { vdx = a2.x; vdy = a2.y; md = 1.f; }
        else if (md > 0.f) { a2.x += vdx; a2.y += vdy; a2.z += 1.f; g_acc[i0 - 2 * Wn] = a2; }
        if (a3.w > 0.5f) { vdx = a3.x; vdy = a3.y; md = 1.f; }
        else if (md > 0.f) { a3.x += vdx; a3.y += vdy; a3.z += 1.f; g_acc[i0 - 3 * Wn] = a3; }
    }

    // forward pass: add "up" contribution, finalize holes
    float vux = 0.f, vuy = 0.f, mu = 0.f;
    float* outX = outp + (size_t)(2 * b    ) * PLANE + x;
    float* outY = outp + (size_t)(2 * b + 1) * PLANE + x;
    for (int y = 0; y < Hn; y += 4) {
        size_t i0 = base + (size_t)y * Wn;
        float4 a0 = g_acc[i0];
        float4 a1 = g_acc[i0 + Wn];
        float4 a2 = g_acc[i0 + 2 * Wn];
        float4 a3 = g_acc[i0 + 3 * Wn];

        #pragma unroll
        for (int k = 0; k < 4; k++) {
            float4 a = (k == 0) ? a0 : (k == 1) ? a1 : (k == 2) ? a2 : a3;
            size_t off = (size_t)(y + k) * Wn;
            if (a.w > 0.5f) {
                vux = a.x; vuy = a.y; mu = 1.f;
            } else {
                float sx = a.x + vux * mu;
                float sy = a.y + vuy * mu;
                float num = a.z + mu;
                float ox = 0.f, oy = 0.f;
                if (num > 0.f) {
                    float inv = 1.f / num;
                    ox = sx * inv;
                    oy = sy * inv;
                }
                outX[off] = ox;
                outY[off] = oy;
            }
        }
    }
}

// ---------------------------------------------------------------- launch
extern "C" void kernel_launch(void* const* d_in, const int* in_sizes, int n_in,
                              void* d_out, int out_size) {
    const float* in = (const float*)d_in[0];
    float* out = (float*)d_out;

    k_zero<<<(NPIX + 255) / 256, 256>>>();

    dim3 gs((PLANE + 255) / 256, Bn);
    k_scatter<<<gs, 256>>>(in);

    k_row<<<Bn * Hn, TPB>>>(out);

    k_col<<<(Bn * Wn + 255) / 256, 256>>>(out);
}

// round 6
// speedup vs baseline: 1.9686x; 1.9686x over previous
#include <cuda_runtime.h>

#define Bn 16
#define Hn 720
#define Wn 1280
#define PLANE (Hn * Wn)
#define NPIX (Bn * PLANE)
#define TPB 256
#define CHUNK 5            // Wn / TPB

#define XT 8               // columns per k_col block
#define SEG 60             // segments per column
#define RSEG 12            // rows per segment (SEG*RSEG == Hn)

// Single-corner splat accumulator: x=sum(-fx), y=sum(-fy), z=count, w=pad.
__device__ float4 g_splat[NPIX];
// Planar partials after row pass:
//   valid pixel: pX,pY = final out values, pNH = -1
//   hole pixel : pX,pY = left/right sums, pNH = left/right count (0..2)
__device__ float g_pX[NPIX];
__device__ float g_pY[NPIX];
__device__ float g_pNH[NPIX];

// ---------------------------------------------------------------- zero
__global__ void k_zero() {
    int i = blockIdx.x * blockDim.x + threadIdx.x;
    if (i < NPIX) g_splat[i] = make_float4(0.f, 0.f, 0.f, 0.f);
}

// ---------------------------------------------------------------- scatter
// One RED.128 per valid source pixel (4 corners = 2x2 box-sum done in k_row).
__global__ void k_scatter(const float* __restrict__ in) {
    int p = blockIdx.x * blockDim.x + threadIdx.x;
    if (p >= PLANE) return;
    int b = blockIdx.y;
    int y = p / Wn;
    int x = p - y * Wn;

    float fx = in[(size_t)(2 * b    ) * PLANE + p];
    float fy = in[(size_t)(2 * b + 1) * PLANE + p];

    float x2 = (float)x + fx;
    float y2 = (float)y + fy;
    if (!(x2 >= 0.f && y2 >= 0.f && x2 <= (float)(Wn - 1) && y2 <= (float)(Hn - 1)))
        return;

    int xL = (int)floorf(x2); xL = max(0, min(xL, Wn - 1));
    int yT = (int)floorf(y2); yT = max(0, min(yT, Hn - 1));

    float4* dst = &g_splat[(size_t)b * PLANE + yT * Wn + xL];
    atomicAdd(dst, make_float4(-fx, -fy, 1.f, 0.f));

    // Degenerate clamp: corners coincide when x2/y2 hit the exact border.
    // True multiplicity at the single corner is (1+ex)*(1+ey); box-sum
    // delivers it once, so add the missing (mult-1)*v.
    int ex = (x2 == (float)(Wn - 1));
    int ey = (y2 == (float)(Hn - 1));
    int m = (1 + ex) * (1 + ey) - 1;
    if (m) atomicAdd(dst, make_float4(-fx * m, -fy * m, (float)m, 0.f));
}

// ------------------------------------- box-sum + normalize + row fill
__global__ void k_row(float* __restrict__ outp) {
    __shared__ float r0x[Wn], r0y[Wn], r0c[Wn];   // splat row y-1
    __shared__ float r1x[Wn], r1y[Wn], r1c[Wn];   // splat row y
    __shared__ float sX[Wn], sY[Wn], sH[Wn];      // normalized
    __shared__ int   sScan[TPB];

    int r = blockIdx.x;          // r = b*Hn + y
    int b = r / Hn;
    int y = r - b * Hn;
    size_t base = (size_t)r * Wn;
    int tid = threadIdx.x;

    // load splat rows y-1 and y
    for (int i = tid; i < Wn; i += TPB) {
        float4 a = g_splat[base + i];
        r1x[i] = a.x; r1y[i] = a.y; r1c[i] = a.z;
        if (y > 0) {
            float4 c = g_splat[base - Wn + i];
            r0x[i] = c.x; r0y[i] = c.y; r0c[i] = c.z;
        } else {
            r0x[i] = 0.f; r0y[i] = 0.f; r0c[i] = 0.f;
        }
    }
    __syncthreads();

    // 2x2 box-sum + normalize
    for (int i = tid; i < Wn; i += TPB) {
        float ax = r1x[i] + r0x[i];
        float ay = r1y[i] + r0y[i];
        float ac = r1c[i] + r0c[i];
        if (i > 0) {
            ax += r1x[i - 1] + r0x[i - 1];
            ay += r1y[i - 1] + r0y[i - 1];
            ac += r1c[i - 1] + r0c[i - 1];
        }
        bool  h   = (ac > 0.f);
        float inv = h ? (1.f / ac) : 0.f;
        sX[i] = ax * inv;
        sY[i] = ay * inv;
        sH[i] = h ? 1.f : 0.f;
    }
    __syncthreads();

    int x0 = tid * CHUNK;

    // left: nearest valid col <= x
    int lloc[CHUNK];
    int lm = -1;
    #pragma unroll
    for (int k = 0; k < CHUNK; k++) {
        int xx = x0 + k;
        if (sH[xx] > 0.f) lm = xx;
        lloc[k] = lm;
    }
    sScan[tid] = lm;
    __syncthreads();
    for (int off = 1; off < TPB; off <<= 1) {
        int v = (tid >= off) ? sScan[tid - off] : -1;
        __syncthreads();
        if (v > sScan[tid]) sScan[tid] = v;
        __syncthreads();
    }
    int carryL = (tid > 0) ? sScan[tid - 1] : -1;
    __syncthreads();

    // right: nearest valid col >= x
    const int BIGI = 1 << 30;
    int rloc[CHUNK];
    int rm = BIGI;
    #pragma unroll
    for (int k = CHUNK - 1; k >= 0; k--) {
        int xx = x0 + k;
        if (sH[xx] > 0.f) rm = xx;
        rloc[k] = rm;
    }
    sScan[tid] = rm;
    __syncthreads();
    for (int off = 1; off < TPB; off <<= 1) {
        int v = (tid + off < TPB) ? sScan[tid + off] : BIGI;
        __syncthreads();
        if (v < sScan[tid]) sScan[tid] = v;
        __syncthreads();
    }
    int carryR = (tid < TPB - 1) ? sScan[tid + 1] : BIGI;

    float* outX = outp + ((size_t)(2 * b    ) * Hn + y) * Wn;
    float* outY = outp + ((size_t)(2 * b + 1) * Hn + y) * Wn;

    #pragma unroll
    for (int k = 0; k < CHUNK; k++) {
        int xx = x0 + k;
        if (sH[xx] > 0.f) {
            float ox = sX[xx], oy = sY[xx];
            outX[xx] = ox;
            outY[xx] = oy;
            g_pX[base + xx]  = ox;
            g_pY[base + xx]  = oy;
            g_pNH[base + xx] = -1.f;
        } else {
            int L = max(carryL, lloc[k]);
            int R = min(carryR, rloc[k]);
            float sx = 0.f, sy = 0.f, num = 0.f;
            if (L >= 0) { sx += sX[L]; sy += sY[L]; num += 1.f; }
            if (R < Wn) { sx += sX[R]; sy += sY[R]; num += 1.f; }
            g_pX[base + xx]  = sx;
            g_pY[base + xx]  = sy;
            g_pNH[base + xx] = num;
        }
    }
}

// ------------------------------------------- parallel column fill
// block = (XT columns, SEG segments); each thread holds RSEG rows in regs.
__global__ void k_col(float* __restrict__ outp) {
    __shared__ float4 sD[SEG][XT];   // down summary -> down carry (in place)
    __shared__ float4 sU[SEG][XT];   // up summary   -> up carry   (in place)

    int tx = threadIdx.x;
    int ts = threadIdx.y;
    int b  = blockIdx.y;
    int gx = blockIdx.x * XT + tx;
    size_t cbase = (size_t)b * PLANE + gx;
    int y0 = ts * RSEG;

    float rx[RSEG], ry[RSEG], rn[RSEG];

    // load segment + per-segment summaries:
    //   down summary = topmost valid in segment; up summary = bottom-most valid.
    float4 dsum = make_float4(0.f, 0.f, 0.f, 0.f);
    float4 usum = make_float4(0.f, 0.f, 0.f, 0.f);
    #pragma unroll
    for (int k = 0; k < RSEG; k++) {
        size_t idx = cbase + (size_t)(y0 + k) * Wn;
        float px = g_pX[idx];
        float py = g_pY[idx];
        float nh = g_pNH[idx];
        rx[k] = px; ry[k] = py; rn[k] = nh;
        if (nh < 0.f) {
            if (dsum.z == 0.f) dsum = make_float4(px, py, 1.f, 0.f);
            usum = make_float4(px, py, 1.f, 0.f);
        }
    }
    sD[ts][tx] = dsum;
    sU[ts][tx] = usum;
    __syncthreads();

    // cross-segment carries (8 threads, serial over SEG; write carry in place)
    if (ts == 0) {
        float4 cur = make_float4(0.f, 0.f, 0.f, 0.f);
        for (int s = SEG - 1; s >= 0; s--) {
            float4 t = sD[s][tx];
            sD[s][tx] = cur;
            if (t.z > 0.f) cur = t;
        }
        cur = make_float4(0.f, 0.f, 0.f, 0.f);
        for (int s = 0; s < SEG; s++) {
            float4 t = sU[s][tx];
            sU[s][tx] = cur;
            if (t.z > 0.f) cur = t;
        }
    }
    __syncthreads();

    // down apply (bottom-up): add nearest-valid-below contribution to holes
    float4 cd = sD[ts][tx];
    #pragma unroll
    for (int k = RSEG - 1; k >= 0; k--) {
        if (rn[k] < 0.f) {
            cd = make_float4(rx[k], ry[k], 1.f, 0.f);
        } else {
            rx[k] += cd.x; ry[k] += cd.y; rn[k] += cd.z;
        }
    }

    // up apply (top-down) + finalize hole outputs
    float4 cu = sU[ts][tx];
    float* oX = outp + (size_t)(2 * b    ) * PLANE + gx;
    float* oY = outp + (size_t)(2 * b + 1) * PLANE + gx;
    #pragma unroll
    for (int k = 0; k < RSEG; k++) {
        if (rn[k] < 0.f) {
            cu = make_float4(rx[k], ry[k], 1.f, 0.f);
        } else {
            float sx  = rx[k] + cu.x;
            float sy  = ry[k] + cu.y;
            float num = rn[k] + cu.z;
            float ox = 0.f, oy = 0.f;
            if (num > 0.f) {
                float inv = 1.f / num;
                ox = sx * inv;
                oy = sy * inv;
            }
            size_t off = (size_t)(y0 + k) * Wn;
            oX[off] = ox;
            oY[off] = oy;
        }
    }
}

// ---------------------------------------------------------------- launch
extern "C" void kernel_launch(void* const* d_in, const int* in_sizes, int n_in,
                              void* d_out, int out_size) {
    const float* in = (const float*)d_in[0];
    float* out = (float*)d_out;

    k_zero<<<(NPIX + 255) / 256, 256>>>();

    dim3 gs((PLANE + 255) / 256, Bn);
    k_scatter<<<gs, 256>>>(in);

    k_row<<<Bn * Hn, TPB>>>(out);

    dim3 gc(Wn / XT, Bn);
    dim3 bc(XT, SEG);
    k_col<<<gc, bc>>>(out);
}

// round 9
// speedup vs baseline: 2.2913x; 1.1639x over previous
#include <cuda_runtime.h>

#define Bn 16
#define Hn 720
#define Wn 1280
#define PLANE (Hn * Wn)
#define NPIX (Bn * PLANE)
#define TPB 256
#define CHUNK 5            // Wn / TPB
#define BIGI (1 << 30)

#define XT 8               // columns per k_col block
#define SEG 120            // segments per column
#define RSEG 6             // rows per segment (SEG*RSEG == Hn)

// Single-corner splat accumulator: x=sum(-fx), y=sum(-fy), z=count, w=pad.
__device__ float4 g_splat[NPIX];
// Compressed planar partials after row pass:
//   valid pixel: pXY = final out values, pNH = -1
//   hole pixel : pXY = left/right sums,  pNH = left/right count (0..2)
__device__ float2 g_pXY[NPIX];
__device__ signed char g_pNH[NPIX];

// ---------------------------------------------------------------- scatter
// One RED.128 per valid source pixel (4 corners = 2x2 box-sum done in k_row).
__global__ void k_scatter(const float* __restrict__ in) {
    int p = blockIdx.x * blockDim.x + threadIdx.x;
    if (p >= PLANE) return;
    int b = blockIdx.y;
    int y = p / Wn;
    int x = p - y * Wn;

    float fx = in[(size_t)(2 * b    ) * PLANE + p];
    float fy = in[(size_t)(2 * b + 1) * PLANE + p];

    float x2 = (float)x + fx;
    float y2 = (float)y + fy;
    if (!(x2 >= 0.f && y2 >= 0.f && x2 <= (float)(Wn - 1) && y2 <= (float)(Hn - 1)))
        return;

    int xL = (int)floorf(x2); xL = max(0, min(xL, Wn - 1));
    int yT = (int)floorf(y2); yT = max(0, min(yT, Hn - 1));

    float4* dst = &g_splat[(size_t)b * PLANE + yT * Wn + xL];
    atomicAdd(dst, make_float4(-fx, -fy, 1.f, 0.f));

    // Degenerate clamp: corners coincide when x2/y2 hit the exact border.
    int ex = (x2 == (float)(Wn - 1));
    int ey = (y2 == (float)(Hn - 1));
    int m = (1 + ex) * (1 + ey) - 1;
    if (m) atomicAdd(dst, make_float4(-fx * m, -fy * m, (float)m, 0.f));
}

// ------------------------------------- box-sum + normalize + row fill
__global__ __launch_bounds__(TPB) void k_row(float* __restrict__ outp) {
    __shared__ float tX[Wn], tY[Wn], tC[Wn];   // vertical pair-sum of splat rows
    __shared__ float sX[Wn], sY[Wn];           // normalized values
    __shared__ int wL[8], wR[8];

    int r = blockIdx.x;          // r = b*Hn + y
    int b = r / Hn;
    int y = r - b * Hn;
    size_t base = (size_t)r * Wn;
    int tid = threadIdx.x;
    int lane = tid & 31;
    int wid = tid >> 5;

    // pass 1: load splat rows y-1,y and fold vertically
    for (int i = tid; i < Wn; i += TPB) {
        float4 a = g_splat[base + i];
        float ax = a.x, ay = a.y, ac = a.z;
        if (y > 0) {
            float4 c = g_splat[base - Wn + i];
            ax += c.x; ay += c.y; ac += c.z;
        }
        tX[i] = ax; tY[i] = ay; tC[i] = ac;
    }
    __syncthreads();

    // pass 2: horizontal box fold + normalize (own chunk), build local scans
    int x0 = tid * CHUNK;
    int lloc[CHUNK], rloc[CHUNK];
    bool hk[CHUNK];
    int lm = -1;
    #pragma unroll
    for (int k = 0; k < CHUNK; k++) {
        int xx = x0 + k;
        float ax = tX[xx], ay = tY[xx], ac = tC[xx];
        if (xx > 0) { ax += tX[xx - 1]; ay += tY[xx - 1]; ac += tC[xx - 1]; }
        bool h = (ac > 0.f);
        float inv = h ? (1.f / ac) : 0.f;
        sX[xx] = ax * inv;
        sY[xx] = ay * inv;
        hk[k] = h;
        if (h) lm = xx;
        lloc[k] = lm;
    }
    int rm = BIGI;
    #pragma unroll
    for (int k = CHUNK - 1; k >= 0; k--) {
        int xx = x0 + k;
        if (hk[k]) rm = xx;
        rloc[k] = rm;
    }

    // warp shuffle scans (inclusive), then cross-warp combine
    int linc = lm;
    #pragma unroll
    for (int off = 1; off < 32; off <<= 1) {
        int v = __shfl_up_sync(0xffffffffu, linc, off);
        if (lane >= off) linc = max(linc, v);
    }
    int rinc = rm;
    #pragma unroll
    for (int off = 1; off < 32; off <<= 1) {
        int v = __shfl_down_sync(0xffffffffu, rinc, off);
        if (lane + off < 32) rinc = min(rinc, v);
    }
    if (lane == 31) wL[wid] = linc;
    if (lane == 0)  wR[wid] = rinc;
    __syncthreads();   // also publishes sX/sY

    int cL = -1;
    for (int w2 = 0; w2 < wid; w2++) cL = max(cL, wL[w2]);
    int le = __shfl_up_sync(0xffffffffu, linc, 1);
    int carryL = max(cL, (lane > 0) ? le : -1);

    int cR = BIGI;
    for (int w2 = wid + 1; w2 < 8; w2++) cR = min(cR, wR[w2]);
    int re = __shfl_down_sync(0xffffffffu, rinc, 1);
    int carryR = min(cR, (lane < 31) ? re : BIGI);

    float* outX = outp + ((size_t)(2 * b    ) * Hn + y) * Wn;
    float* outY = outp + ((size_t)(2 * b + 1) * Hn + y) * Wn;

    #pragma unroll
    for (int k = 0; k < CHUNK; k++) {
        int xx = x0 + k;
        int L = max(carryL, lloc[k]);
        int R = min(carryR, rloc[k]);
        if (L == xx) {     // valid pixel
            float ox = sX[xx], oy = sY[xx];
            outX[xx] = ox;
            outY[xx] = oy;
            g_pXY[base + xx] = make_float2(ox, oy);
            g_pNH[base + xx] = (signed char)(-1);
        } else {           // hole: left/right partial
            float sx = 0.f, sy = 0.f;
            int num = 0;
            if (L >= 0) { sx += sX[L]; sy += sY[L]; num++; }
            if (R < Wn) { sx += sX[R]; sy += sY[R]; num++; }
            g_pXY[base + xx] = make_float2(sx, sy);
            g_pNH[base + xx] = (signed char)num;
        }
    }
}

// ------------------------------------------- parallel column fill
// block = (XT columns, SEG segments); each thread holds RSEG rows in regs.
__global__ __launch_bounds__(XT * SEG, 1) void k_col(float* __restrict__ outp) {
    __shared__ float4 sD[SEG][XT];   // "first valid at/below" scan
    __shared__ float4 sU[SEG][XT];   // "last valid at/above" scan

    int tx = threadIdx.x;
    int ts = threadIdx.y;
    int b  = blockIdx.y;
    int gx = blockIdx.x * XT + tx;
    size_t cbase = (size_t)b * PLANE + gx;
    int y0 = ts * RSEG;

    float rx[RSEG], ry[RSEG], rn[RSEG];

    float4 dsum = make_float4(0.f, 0.f, 0.f, 0.f);   // topmost valid in seg
    float4 usum = make_float4(0.f, 0.f, 0.f, 0.f);   // bottom-most valid in seg
    #pragma unroll
    for (int k = 0; k < RSEG; k++) {
        size_t idx = cbase + (size_t)(y0 + k) * Wn;
        float2 pv = g_pXY[idx];
        signed char nh = g_pNH[idx];
        rx[k] = pv.x; ry[k] = pv.y;
        if (nh < 0) {
            rn[k] = -1.f;
            if (dsum.z == 0.f) dsum = make_float4(pv.x, pv.y, 1.f, 0.f);
            usum = make_float4(pv.x, pv.y, 1.f, 0.f);
        } else {
            rn[k] = (float)nh;
        }
    }
    sD[ts][tx] = dsum;
    sU[ts][tx] = usum;
    __syncthreads();

    // Hillis-Steele "nearest valid" scans along segments (both directions)
    for (int off = 1; off < SEG; off <<= 1) {
        float4 myD = sD[ts][tx];
        float4 myU = sU[ts][tx];
        float4 dv = (ts + off < SEG) ? sD[ts + off][tx] : make_float4(0.f, 0.f, 0.f, 0.f);
        float4 uv = (ts >= off)      ? sU[ts - off][tx] : make_float4(0.f, 0.f, 0.f, 0.f);
        __syncthreads();
        if (myD.z == 0.f) sD[ts][tx] = dv;
        if (myU.z == 0.f) sU[ts][tx] = uv;
        __syncthreads();
    }

    float4 cd = (ts + 1 < SEG) ? sD[ts + 1][tx] : make_float4(0.f, 0.f, 0.f, 0.f);
    float4 cu = (ts > 0)       ? sU[ts - 1][tx] : make_float4(0.f, 0.f, 0.f, 0.f);

    // down apply (bottom-up)
    #pragma unroll
    for (int k = RSEG - 1; k >= 0; k--) {
        if (rn[k] < 0.f) {
            cd = make_float4(rx[k], ry[k], 1.f, 0.f);
        } else {
            rx[k] += cd.x; ry[k] += cd.y; rn[k] += cd.z;
        }
    }

    // up apply (top-down) + finalize hole outputs
    float* oX = outp + (size_t)(2 * b    ) * PLANE + gx;
    float* oY = outp + (size_t)(2 * b + 1) * PLANE + gx;
    #pragma unroll
    for (int k = 0; k < RSEG; k++) {
        if (rn[k] < 0.f) {
            cu = make_float4(rx[k], ry[k], 1.f, 0.f);
        } else {
            float sx  = rx[k] + cu.x;
            float sy  = ry[k] + cu.y;
            float num = rn[k] + cu.z;
            float ox = 0.f, oy = 0.f;
            if (num > 0.f) {
                float inv = 1.f / num;
                ox = sx * inv;
                oy = sy * inv;
            }
            size_t off = (size_t)(y0 + k) * Wn;
            oX[off] = ox;
            oY[off] = oy;
        }
    }
}

// ---------------------------------------------------------------- launch
extern "C" void kernel_launch(void* const* d_in, const int* in_sizes, int n_in,
                              void* d_out, int out_size) {
    const float* in = (const float*)d_in[0];
    float* out = (float*)d_out;

    void* splat_ptr = nullptr;
    cudaGetSymbolAddress(&splat_ptr, g_splat);
    cudaMemsetAsync(splat_ptr, 0, (size_t)NPIX * sizeof(float4));

    dim3 gs((PLANE + 255) / 256, Bn);
    k_scatter<<<gs, 256>>>(in);

    k_row<<<Bn * Hn, TPB>>>(out);

    dim3 gc(Wn / XT, Bn);
    dim3 bc(XT, SEG);
    k_col<<<gc, bc>>>(out);
}